// round 8
// baseline (speedup 1.0000x reference)
#include <cuda_runtime.h>
#include <cuda_fp16.h>
#include <math.h>
#include <stdint.h>

#define B_  2
#define L_  1024
#define D_  1024
#define H_  16
#define R_  16
#define DK_ 64
#define F_  4096
#define NL_ 4
#define ROWS_ (B_*L_)
#define QSTR (3*D_)

// ---------------- scratch (no runtime allocation allowed) ----------------
__device__ float  g_x  [ROWS_*D_];
__device__ __half g_h  [ROWS_*D_];
__device__ __half g_qkv[ROWS_*3*D_];
__device__ __half g_ctx[ROWS_*D_];
__device__ __half g_ff [ROWS_*F_];
__device__ __half g_wt_attn[(size_t)NL_*4*D_*D_];
__device__ __half g_wt_ff1 [(size_t)NL_*D_*F_];
__device__ __half g_wt_ff2 [(size_t)NL_*F_*D_];

// ---------------- helpers -------------------------------------------------
__device__ __forceinline__ uint32_t smem_to_u32(const void* p) {
    uint32_t a;
    asm("{ .reg .u64 t; cvta.to.shared.u64 t, %1; cvt.u32.u64 %0, t; }" : "=r"(a) : "l"(p));
    return a;
}
__device__ __forceinline__ void cp16(uint32_t dst, const void* src) {
    asm volatile("cp.async.cg.shared.global [%0], [%1], 16;" :: "r"(dst), "l"(src));
}
__device__ __forceinline__ void ldsm_x4(uint32_t* r, uint32_t addr) {
    asm volatile("ldmatrix.sync.aligned.m8n8.x4.shared.b16 {%0,%1,%2,%3}, [%4];"
        : "=r"(r[0]), "=r"(r[1]), "=r"(r[2]), "=r"(r[3]) : "r"(addr));
}
__device__ __forceinline__ void mma_f16(float* c, const uint32_t* a, const uint32_t* b) {
    asm volatile(
        "mma.sync.aligned.m16n8k16.row.col.f32.f16.f16.f32 "
        "{%0,%1,%2,%3}, {%4,%5,%6,%7}, {%8,%9}, {%0,%1,%2,%3};"
        : "+f"(c[0]), "+f"(c[1]), "+f"(c[2]), "+f"(c[3])
        : "r"(a[0]), "r"(a[1]), "r"(a[2]), "r"(a[3]), "r"(b[0]), "r"(b[1]));
}
__device__ __forceinline__ float gelu_f(float x) {
    float x3 = x * x * x;
    return 0.5f * x * (1.0f + tanhf(0.7978845608028654f * (x + 0.044715f * x3)));
}

// ---------------- weight transpose (src [K][N] f32 -> dst [N][K] f16) ------
__global__ __launch_bounds__(256) void transpose_k(
    const float* __restrict__ src, __half* __restrict__ dst, int K, int N)
{
    __shared__ float t[32][33];
    src += (size_t)blockIdx.z * K * N;
    dst += (size_t)blockIdx.z * K * N;
    int n0 = blockIdx.x * 32, k0 = blockIdx.y * 32;
    int tx = threadIdx.x, ty = threadIdx.y;
    #pragma unroll
    for (int i = 0; i < 32; i += 8)
        t[ty + i][tx] = src[(size_t)(k0 + ty + i) * N + n0 + tx];
    __syncthreads();
    #pragma unroll
    for (int i = 0; i < 32; i += 8)
        dst[(size_t)(n0 + ty + i) * K + k0 + tx] = __float2half_rn(t[tx][ty + i]);
}

// ---------------- fp16 mma.sync GEMM: C[M,N] = A[M,K] * Bt[N,K]^T ----------
// CTA 128x64, 8 warps (warp tile 32x32, 4x2 grid), BK=64 fp16, 4-stage
// cp.async, 2 CTAs/SM (110.6KB smem each), low reg pressure (acc=32/thread).
#define BKG   64             // K elements per stage (128 bytes fp16)
#define ROWB  144            // bytes per smem row (128B data + 16B pad)
#define A_ROWS 128
#define B_ROWS 64
#define A_BYTES (A_ROWS*ROWB)            // 18432
#define STAGE ((A_ROWS+B_ROWS)*ROWB)     // 27648
#define NSTG  4
#define GEMM_SMEM (NSTG*STAGE)           // 110592

__global__ __launch_bounds__(256, 2) void tc_gemm(
    const __half* __restrict__ A, const __half* __restrict__ Bt,
    const float* __restrict__ bias, const float* __restrict__ res,
    void* __restrict__ Cp, int M, int N, int K, int do_gelu, int out_half)
{
    extern __shared__ char smem[];
    const uint32_t sb = smem_to_u32(smem);
    const int tid  = threadIdx.x;
    const int wid  = tid >> 5;
    const int lane = tid & 31;

    const int m0 = blockIdx.y * 128;
    const int n0 = blockIdx.x * 64;
    const int KT = K / BKG;

    const int warp_m = (wid >> 1) * 32;      // 0,32,64,96
    const int warp_n = (wid & 1) * 32;       // 0 or 32

    // A m16k16 x4: lanes 0-15 -> rows, lanes 16-31 -> +16B k-seg
    const uint32_t a_off = (uint32_t)(warp_m + (lane & 15)) * ROWB
                         + (uint32_t)(lane >> 4) * 16;
    // B x4 (two n8 frags): lanes0-7 rows seg0, 8-15 rows seg1,
    //                      16-23 rows+8 seg0, 24-31 rows+8 seg1
    const uint32_t b_off = (uint32_t)(warp_n + (lane & 7) + ((lane >> 4) << 3)) * ROWB
                         + (uint32_t)((lane >> 3) & 1) * 16;

    float acc[2][4][4];
    #pragma unroll
    for (int i = 0; i < 2; i++)
        #pragma unroll
        for (int j = 0; j < 4; j++)
            #pragma unroll
            for (int v = 0; v < 4; v++) acc[i][j][v] = 0.0f;

    // --- stage loader: 4 A-chunks + 2 B-chunks of 16B per thread (256 thr) ---
    auto load_stage = [&](int kt) {
        if (kt >= KT) return;
        int s = kt & (NSTG - 1);
        uint32_t dA = sb + s * STAGE;
        uint32_t dB = dA + A_BYTES;
        int kbase = kt * BKG;
        #pragma unroll
        for (int i = 0; i < 4; i++) {
            int c = tid + i * 256;             // 0..1023
            int row = c >> 3, kk = c & 7;
            cp16(dA + row * ROWB + kk * 16,
                 A + (size_t)(m0 + row) * K + kbase + kk * 8);
        }
        #pragma unroll
        for (int i = 0; i < 2; i++) {
            int c = tid + i * 256;             // 0..511
            int row = c >> 3, kk = c & 7;
            cp16(dB + row * ROWB + kk * 16,
                 Bt + (size_t)(n0 + row) * K + kbase + kk * 8);
        }
    };

    load_stage(0); asm volatile("cp.async.commit_group;");
    load_stage(1); asm volatile("cp.async.commit_group;");
    load_stage(2); asm volatile("cp.async.commit_group;");

    for (int kt = 0; kt < KT; kt++) {
        asm volatile("cp.async.wait_group 2;");
        __syncthreads();

        int s = kt & (NSTG - 1);
        uint32_t sA = sb + s * STAGE;
        uint32_t sB = sA + A_BYTES;

        #pragma unroll
        for (int ks = 0; ks < 4; ks++) {       // 4 x k16 steps = BK 64
            uint32_t a[2][4], b[4][2];
            #pragma unroll
            for (int mt = 0; mt < 2; mt++)
                ldsm_x4(a[mt], sA + a_off + (uint32_t)mt * (16 * ROWB) + ks * 32);
            #pragma unroll
            for (int g = 0; g < 2; g++) {
                uint32_t t4[4];
                ldsm_x4(t4, sB + b_off + (uint32_t)g * (16 * ROWB) + ks * 32);
                b[2*g][0] = t4[0]; b[2*g][1] = t4[1];
                b[2*g+1][0] = t4[2]; b[2*g+1][1] = t4[3];
            }
            #pragma unroll
            for (int mt = 0; mt < 2; mt++)
                #pragma unroll
                for (int nt = 0; nt < 4; nt++)
                    mma_f16(acc[mt][nt], a[mt], b[nt]);
        }

        // prefetch stage kt+3 -> slot (kt+3)%4 == (kt-1)%4, consumed before the
        // sync above in every warp's program order
        load_stage(kt + 3);
        asm volatile("cp.async.commit_group;");
    }

    // ---------------- epilogue ----------------
    const int rbase = m0 + warp_m + (lane >> 2);
    const int cbase = n0 + warp_n + 2 * (lane & 3);
    #pragma unroll
    for (int mt = 0; mt < 2; mt++) {
        #pragma unroll
        for (int nt = 0; nt < 4; nt++) {
            int col = cbase + nt * 8;
            float2 bi = *(const float2*)(bias + col);
            #pragma unroll
            for (int half = 0; half < 2; half++) {
                int row = rbase + mt * 16 + half * 8;
                size_t ro = (size_t)row * N + col;
                float ox = acc[mt][nt][2 * half + 0] + bi.x;
                float oy = acc[mt][nt][2 * half + 1] + bi.y;
                if (do_gelu) { ox = gelu_f(ox); oy = gelu_f(oy); }
                if (res) {
                    float2 rv = *(const float2*)(res + ro);
                    ox += rv.x; oy += rv.y;
                }
                if (out_half) {
                    *(__half2*)((__half*)Cp + ro) = __floats2half2_rn(ox, oy);
                } else {
                    *(float2*)((float*)Cp + ro) = make_float2(ox, oy);
                }
            }
        }
    }
}

// ---------------- LayerNorm: one block per row, D=1024, 256 thr ----------
__global__ __launch_bounds__(256) void ln_kernel(
    const float* __restrict__ x, const float* __restrict__ g,
    const float* __restrict__ b, void* __restrict__ out, int out_half)
{
    int row = blockIdx.x;
    int t = threadIdx.x;
    const float4* xr = (const float4*)(x + (size_t)row * D_);
    float4 v = xr[t];

    __shared__ float red[8];
    float s = v.x + v.y + v.z + v.w;
    #pragma unroll
    for (int o = 16; o; o >>= 1) s += __shfl_xor_sync(0xffffffffu, s, o);
    if ((t & 31) == 0) red[t >> 5] = s;
    __syncthreads();
    float tot = red[0];
    #pragma unroll
    for (int w = 1; w < 8; w++) tot += red[w];
    float mu = tot * (1.0f / D_);
    float dx = v.x - mu, dy = v.y - mu, dz = v.z - mu, dw = v.w - mu;
    __syncthreads();
    float s2 = dx*dx + dy*dy + dz*dz + dw*dw;
    #pragma unroll
    for (int o = 16; o; o >>= 1) s2 += __shfl_xor_sync(0xffffffffu, s2, o);
    if ((t & 31) == 0) red[t >> 5] = s2;
    __syncthreads();
    float tot2 = red[0];
    #pragma unroll
    for (int w = 1; w < 8; w++) tot2 += red[w];
    float rstd = rsqrtf(tot2 * (1.0f / D_) + 1e-5f);

    float4 gv = ((const float4*)g)[t];
    float4 bv = ((const float4*)b)[t];
    float ox = dx * rstd * gv.x + bv.x;
    float oy = dy * rstd * gv.y + bv.y;
    float oz = dz * rstd * gv.z + bv.z;
    float ow = dw * rstd * gv.w + bv.w;
    if (out_half) {
        __half2* po = (__half2*)((__half*)out + (size_t)row * D_) + t * 2;
        po[0] = __floats2half2_rn(ox, oy);
        po[1] = __floats2half2_rn(oz, ow);
    } else {
        ((float4*)((float*)out + (size_t)row * D_))[t] = make_float4(ox, oy, oz, ow);
    }
}

// ---------------- tree-relative attention: one warp per (b,h,l) ----------
__global__ __launch_bounds__(256) void attn_kernel(
    const __half* __restrict__ qkv, const int* __restrict__ pos,
    const float* __restrict__ rq, const float* __restrict__ rk,
    const float* __restrict__ rv, __half* __restrict__ ctx)
{
    int gw   = blockIdx.x * (blockDim.x >> 5) + (threadIdx.x >> 5);
    int lane = threadIdx.x & 31;
    int l  = gw & (L_ - 1);
    int bh = gw >> 10;
    int h  = bh & (H_ - 1);
    int b  = bh >> 4;

    size_t qoff = (size_t)(b * L_ + l) * QSTR + h * DK_ + lane * 2;
    float2 qv = __half22float2(*(const __half2*)(qkv + qoff));
    const int* pp = pos + ((size_t)(b * H_ + h) * R_) * L_ + l;
    const __half* kb = qkv + D_   + (size_t)h * DK_ + lane * 2;
    const __half* vb = qkv + 2*D_ + (size_t)h * DK_ + lane * 2;

    float sc[R_];
    int   idxs[R_];
    #pragma unroll
    for (int r = 0; r < R_; r++) {
        int idx = pp[(size_t)r * L_];
        idxs[r] = idx;
        float2 rqv = *(const float2*)(rq + (h * R_ + r) * DK_ + lane * 2);
        float2 rkv = *(const float2*)(rk + (h * R_ + r) * DK_ + lane * 2);
        float2 kg  = __half22float2(*(const __half2*)(kb + (size_t)(b * L_ + idx) * QSTR));
        float p = (qv.x + rqv.x) * kg.x + (qv.y + rqv.y) * kg.y
                +  qv.x * rkv.x + qv.y * rkv.y;
        #pragma unroll
        for (int o = 16; o; o >>= 1) p += __shfl_xor_sync(0xffffffffu, p, o);
        sc[r] = (idx != l) ? p * 0.125f : -1e9f;
    }

    float m = sc[0];
    #pragma unroll
    for (int r = 1; r < R_; r++) m = fmaxf(m, sc[r]);
    float s = 0.0f;
    #pragma unroll
    for (int r = 0; r < R_; r++) { sc[r] = __expf(sc[r] - m); s += sc[r]; }
    float inv = 1.0f / s;

    float ax = 0.0f, ay = 0.0f;
    #pragma unroll
    for (int r = 0; r < R_; r++) {
        float a = sc[r] * inv;
        float2 rvv = *(const float2*)(rv + (h * R_ + r) * DK_ + lane * 2);
        float2 vg  = __half22float2(*(const __half2*)(vb + (size_t)(b * L_ + idxs[r]) * QSTR));
        ax = fmaf(a, vg.x + rvv.x, ax);
        ay = fmaf(a, vg.y + rvv.y, ay);
    }
    size_t coff = (size_t)(b * L_ + l) * D_ + h * DK_ + lane * 2;
    *(__half2*)(ctx + coff) = __floats2half2_rn(ax, ay);
}

// ---------------- host orchestration -------------------------------------
extern "C" void kernel_launch(void* const* d_in, const int* in_sizes, int n_in,
                              void* d_out, int out_size)
{
    const float* emb    = (const float*)d_in[0];
    const int*   pos    = (const int*)  d_in[1];
    const float* rel_q  = (const float*)d_in[2];
    const float* rel_k  = (const float*)d_in[3];
    const float* rel_v  = (const float*)d_in[4];
    const float* attn_w = (const float*)d_in[5];
    const float* attn_b = (const float*)d_in[6];
    const float* ff_w1  = (const float*)d_in[7];
    const float* ff_b1  = (const float*)d_in[8];
    const float* ff_w2  = (const float*)d_in[9];
    const float* ff_b2  = (const float*)d_in[10];
    const float* ln_g   = (const float*)d_in[11];
    const float* ln_b   = (const float*)d_in[12];
    const float* fin_g  = (const float*)d_in[13];
    const float* fin_b  = (const float*)d_in[14];
    float* out = (float*)d_out;

    float *x;
    __half *h, *qkv, *ctx, *ff, *wta, *wtf1, *wtf2;
    cudaGetSymbolAddress((void**)&x,    g_x);
    cudaGetSymbolAddress((void**)&h,    g_h);
    cudaGetSymbolAddress((void**)&qkv,  g_qkv);
    cudaGetSymbolAddress((void**)&ctx,  g_ctx);
    cudaGetSymbolAddress((void**)&ff,   g_ff);
    cudaGetSymbolAddress((void**)&wta,  g_wt_attn);
    cudaGetSymbolAddress((void**)&wtf1, g_wt_ff1);
    cudaGetSymbolAddress((void**)&wtf2, g_wt_ff2);

    static bool attr_done = false;
    if (!attr_done) {
        cudaFuncSetAttribute(tc_gemm, cudaFuncAttributeMaxDynamicSharedMemorySize, GEMM_SMEM);
        attr_done = true;
    }

    // ---- weight transposes: W[K][N] f32 -> Wt[N][K] f16 ----
    transpose_k<<<dim3(D_/32, D_/32, NL_*4), dim3(32,8)>>>(attn_w, wta,  D_, D_);
    transpose_k<<<dim3(F_/32, D_/32, NL_),   dim3(32,8)>>>(ff_w1,  wtf1, D_, F_);
    transpose_k<<<dim3(D_/32, F_/32, NL_),   dim3(32,8)>>>(ff_w2,  wtf2, F_, D_);

    dim3 gQKV(3*D_/64, ROWS_/128);    // (48, 16) = 768 CTAs
    dim3 gD(D_/64, ROWS_/128);        // (16, 16) = 256 CTAs
    dim3 gF(F_/64, ROWS_/128);        // (64, 16) = 1024 CTAs
    int attn_blocks = (B_ * H_ * L_) / 8;

    for (int i = 0; i < NL_; i++) {
        const float* xin = (i == 0) ? emb : x;
        const __half* Wt = wta + (size_t)i * 4 * D_ * D_;
        const float* Bb = attn_b + (size_t)i * 4 * D_;

        ln_kernel<<<ROWS_, 256>>>(xin, ln_g + (size_t)(i*2) * D_, ln_b + (size_t)(i*2) * D_, h, 1);

        tc_gemm<<<gQKV, 256, GEMM_SMEM>>>(h, Wt, Bb, nullptr, qkv, ROWS_, QSTR, D_, 0, 1);

        attn_kernel<<<attn_blocks, 256>>>(qkv, pos, rel_q, rel_k, rel_v, ctx);

        tc_gemm<<<gD, 256, GEMM_SMEM>>>(ctx, Wt + (size_t)3*D_*D_, Bb + 3*D_, xin, x, ROWS_, D_, D_, 0, 0);

        ln_kernel<<<ROWS_, 256>>>(x, ln_g + (size_t)(i*2+1) * D_, ln_b + (size_t)(i*2+1) * D_, h, 1);

        tc_gemm<<<gF, 256, GEMM_SMEM>>>(h,  wtf1 + (size_t)i * D_ * F_, ff_b1 + (size_t)i * F_,
                                        nullptr, ff, ROWS_, F_, D_, 1, 1);
        tc_gemm<<<gD, 256, GEMM_SMEM>>>(ff, wtf2 + (size_t)i * F_ * D_, ff_b2 + (size_t)i * D_,
                                        x, x, ROWS_, D_, F_, 0, 0);
    }
    ln_kernel<<<ROWS_, 256>>>(x, fin_g, fin_b, out, 0);
}

// round 9
// speedup vs baseline: 1.0220x; 1.0220x over previous
#include <cuda_runtime.h>
#include <cuda_fp16.h>
#include <math.h>
#include <stdint.h>

#define B_  2
#define L_  1024
#define D_  1024
#define H_  16
#define R_  16
#define DK_ 64
#define F_  4096
#define NL_ 4
#define ROWS_ (B_*L_)
#define QSTR (3*D_)

// ---------------- scratch (no runtime allocation allowed) ----------------
__device__ float  g_x  [ROWS_*D_];
__device__ __half g_h  [ROWS_*D_];
__device__ __half g_qkv[ROWS_*3*D_];
__device__ __half g_ctx[ROWS_*D_];
__device__ __half g_ff [ROWS_*F_];
__device__ __half g_wt_attn[(size_t)NL_*4*D_*D_];
__device__ __half g_wt_ff1 [(size_t)NL_*D_*F_];
__device__ __half g_wt_ff2 [(size_t)NL_*F_*D_];

// ---------------- helpers -------------------------------------------------
__device__ __forceinline__ uint32_t smem_to_u32(const void* p) {
    uint32_t a;
    asm("{ .reg .u64 t; cvta.to.shared.u64 t, %1; cvt.u32.u64 %0, t; }" : "=r"(a) : "l"(p));
    return a;
}
__device__ __forceinline__ void cp16(uint32_t dst, const void* src) {
    asm volatile("cp.async.cg.shared.global [%0], [%1], 16;" :: "r"(dst), "l"(src));
}
__device__ __forceinline__ void ldsm_x4(uint32_t* r, uint32_t addr) {
    asm volatile("ldmatrix.sync.aligned.m8n8.x4.shared.b16 {%0,%1,%2,%3}, [%4];"
        : "=r"(r[0]), "=r"(r[1]), "=r"(r[2]), "=r"(r[3]) : "r"(addr));
}
__device__ __forceinline__ void mma_f16(float* c, const uint32_t* a, const uint32_t* b) {
    asm volatile(
        "mma.sync.aligned.m16n8k16.row.col.f32.f16.f16.f32 "
        "{%0,%1,%2,%3}, {%4,%5,%6,%7}, {%8,%9}, {%0,%1,%2,%3};"
        : "+f"(c[0]), "+f"(c[1]), "+f"(c[2]), "+f"(c[3])
        : "r"(a[0]), "r"(a[1]), "r"(a[2]), "r"(a[3]), "r"(b[0]), "r"(b[1]));
}
__device__ __forceinline__ float gelu_f(float x) {
    float x3 = x * x * x;
    return 0.5f * x * (1.0f + tanhf(0.7978845608028654f * (x + 0.044715f * x3)));
}

// ---------------- weight transpose (src [K][N] f32 -> dst [N][K] f16) ------
__global__ __launch_bounds__(256) void transpose_k(
    const float* __restrict__ src, __half* __restrict__ dst, int K, int N)
{
    __shared__ float t[32][33];
    src += (size_t)blockIdx.z * K * N;
    dst += (size_t)blockIdx.z * K * N;
    int n0 = blockIdx.x * 32, k0 = blockIdx.y * 32;
    int tx = threadIdx.x, ty = threadIdx.y;
    #pragma unroll
    for (int i = 0; i < 32; i += 8)
        t[ty + i][tx] = src[(size_t)(k0 + ty + i) * N + n0 + tx];
    __syncthreads();
    #pragma unroll
    for (int i = 0; i < 32; i += 8)
        dst[(size_t)(n0 + ty + i) * K + k0 + tx] = __float2half_rn(t[tx][ty + i]);
}

// ---------------- shared GEMM constants ----------------
#define BKG   64             // K elements per stage (128 bytes fp16)
#define ROWB  144            // bytes per smem row (128B data + 16B pad)
#define GEMM_SMEM 110592

// ======== GEMM-A: CTA 128x128, 8 warps (64x32), 3-stage, 2 CTA/SM ========
#define HALF_A (128*ROWB)          // 18432
#define STAGE_A (2*HALF_A)         // 36864  (x3 = 110592)

__global__ __launch_bounds__(256, 2) void tc_gemm128(
    const __half* __restrict__ A, const __half* __restrict__ Bt,
    const float* __restrict__ bias, const float* __restrict__ res,
    void* __restrict__ Cp, int M, int N, int K, int do_gelu, int out_half)
{
    extern __shared__ char smem[];
    const uint32_t sb = smem_to_u32(smem);
    const int tid  = threadIdx.x;
    const int wid  = tid >> 5;
    const int lane = tid & 31;

    const int m0 = blockIdx.y * 128;
    const int n0 = blockIdx.x * 128;
    const int KT = K / BKG;

    const int warp_m = (wid >> 2) * 64;
    const int warp_n = (wid & 3) * 32;

    const uint32_t a_off = (uint32_t)(warp_m + (lane & 15)) * ROWB
                         + (uint32_t)(lane >> 4) * 16;
    const uint32_t b_off = (uint32_t)(warp_n + (lane & 7) + ((lane >> 4) << 3)) * ROWB
                         + (uint32_t)((lane >> 3) & 1) * 16;

    float acc[4][4][4];
    #pragma unroll
    for (int i = 0; i < 4; i++)
        #pragma unroll
        for (int j = 0; j < 4; j++)
            #pragma unroll
            for (int v = 0; v < 4; v++) acc[i][j][v] = 0.0f;

    auto load_stage = [&](int kt) {
        if (kt >= KT) return;
        int s = kt % 3;
        uint32_t dA = sb + s * STAGE_A;
        uint32_t dB = dA + HALF_A;
        int kbase = kt * BKG;
        #pragma unroll
        for (int i = 0; i < 4; i++) {
            int c = tid + i * 256;
            int row = c >> 3, kk = c & 7;
            cp16(dA + row * ROWB + kk * 16,
                 A + (size_t)(m0 + row) * K + kbase + kk * 8);
        }
        #pragma unroll
        for (int i = 0; i < 4; i++) {
            int c = tid + i * 256;
            int row = c >> 3, kk = c & 7;
            cp16(dB + row * ROWB + kk * 16,
                 Bt + (size_t)(n0 + row) * K + kbase + kk * 8);
        }
    };

    load_stage(0); asm volatile("cp.async.commit_group;");
    load_stage(1); asm volatile("cp.async.commit_group;");

    for (int kt = 0; kt < KT; kt++) {
        asm volatile("cp.async.wait_group 1;");
        __syncthreads();

        int s = kt % 3;
        uint32_t sA = sb + s * STAGE_A;
        uint32_t sB = sA + HALF_A;

        #pragma unroll
        for (int ks = 0; ks < 4; ks++) {
            uint32_t a[4][4], b[4][2];
            #pragma unroll
            for (int mt = 0; mt < 4; mt++)
                ldsm_x4(a[mt], sA + a_off + (uint32_t)mt * (16 * ROWB) + ks * 32);
            #pragma unroll
            for (int g = 0; g < 2; g++) {
                uint32_t t4[4];
                ldsm_x4(t4, sB + b_off + (uint32_t)g * (16 * ROWB) + ks * 32);
                b[2*g][0] = t4[0]; b[2*g][1] = t4[1];
                b[2*g+1][0] = t4[2]; b[2*g+1][1] = t4[3];
            }
            #pragma unroll
            for (int mt = 0; mt < 4; mt++)
                #pragma unroll
                for (int nt = 0; nt < 4; nt++)
                    mma_f16(acc[mt][nt], a[mt], b[nt]);
        }

        load_stage(kt + 2);
        asm volatile("cp.async.commit_group;");
    }

    const int rbase = m0 + warp_m + (lane >> 2);
    const int cbase = n0 + warp_n + 2 * (lane & 3);
    #pragma unroll
    for (int mt = 0; mt < 4; mt++) {
        #pragma unroll
        for (int nt = 0; nt < 4; nt++) {
            int col = cbase + nt * 8;
            float2 bi = *(const float2*)(bias + col);
            #pragma unroll
            for (int half = 0; half < 2; half++) {
                int row = rbase + mt * 16 + half * 8;
                size_t ro = (size_t)row * N + col;
                float ox = acc[mt][nt][2 * half + 0] + bi.x;
                float oy = acc[mt][nt][2 * half + 1] + bi.y;
                if (do_gelu) { ox = gelu_f(ox); oy = gelu_f(oy); }
                if (res) {
                    float2 rv = *(const float2*)(res + ro);
                    ox += rv.x; oy += rv.y;
                }
                if (out_half) {
                    *(__half2*)((__half*)Cp + ro) = __floats2half2_rn(ox, oy);
                } else {
                    *(float2*)((float*)Cp + ro) = make_float2(ox, oy);
                }
            }
        }
    }
}

// ======== GEMM-B: CTA 128x64, 8 warps (32x32), 4-stage, 2 CTA/SM =========
// for the 1024-wide GEMMs (O-proj, FF2) whose 128^2 grids under-fill the chip
#define A_BYTES_B (128*ROWB)               // 18432
#define STAGE_B ((128+64)*ROWB)            // 27648 (x4 = 110592)

__global__ __launch_bounds__(256, 2) void tc_gemm64(
    const __half* __restrict__ A, const __half* __restrict__ Bt,
    const float* __restrict__ bias, const float* __restrict__ res,
    void* __restrict__ Cp, int M, int N, int K, int do_gelu, int out_half)
{
    extern __shared__ char smem[];
    const uint32_t sb = smem_to_u32(smem);
    const int tid  = threadIdx.x;
    const int wid  = tid >> 5;
    const int lane = tid & 31;

    const int m0 = blockIdx.y * 128;
    const int n0 = blockIdx.x * 64;
    const int KT = K / BKG;

    const int warp_m = (wid >> 1) * 32;
    const int warp_n = (wid & 1) * 32;

    const uint32_t a_off = (uint32_t)(warp_m + (lane & 15)) * ROWB
                         + (uint32_t)(lane >> 4) * 16;
    const uint32_t b_off = (uint32_t)(warp_n + (lane & 7) + ((lane >> 4) << 3)) * ROWB
                         + (uint32_t)((lane >> 3) & 1) * 16;

    float acc[2][4][4];
    #pragma unroll
    for (int i = 0; i < 2; i++)
        #pragma unroll
        for (int j = 0; j < 4; j++)
            #pragma unroll
            for (int v = 0; v < 4; v++) acc[i][j][v] = 0.0f;

    auto load_stage = [&](int kt) {
        if (kt >= KT) return;
        int s = kt & 3;
        uint32_t dA = sb + s * STAGE_B;
        uint32_t dB = dA + A_BYTES_B;
        int kbase = kt * BKG;
        #pragma unroll
        for (int i = 0; i < 4; i++) {
            int c = tid + i * 256;
            int row = c >> 3, kk = c & 7;
            cp16(dA + row * ROWB + kk * 16,
                 A + (size_t)(m0 + row) * K + kbase + kk * 8);
        }
        #pragma unroll
        for (int i = 0; i < 2; i++) {
            int c = tid + i * 256;
            int row = c >> 3, kk = c & 7;
            cp16(dB + row * ROWB + kk * 16,
                 Bt + (size_t)(n0 + row) * K + kbase + kk * 8);
        }
    };

    load_stage(0); asm volatile("cp.async.commit_group;");
    load_stage(1); asm volatile("cp.async.commit_group;");
    load_stage(2); asm volatile("cp.async.commit_group;");

    for (int kt = 0; kt < KT; kt++) {
        asm volatile("cp.async.wait_group 2;");
        __syncthreads();

        int s = kt & 3;
        uint32_t sA = sb + s * STAGE_B;
        uint32_t sB = sA + A_BYTES_B;

        #pragma unroll
        for (int ks = 0; ks < 4; ks++) {
            uint32_t a[2][4], b[4][2];
            #pragma unroll
            for (int mt = 0; mt < 2; mt++)
                ldsm_x4(a[mt], sA + a_off + (uint32_t)mt * (16 * ROWB) + ks * 32);
            #pragma unroll
            for (int g = 0; g < 2; g++) {
                uint32_t t4[4];
                ldsm_x4(t4, sB + b_off + (uint32_t)g * (16 * ROWB) + ks * 32);
                b[2*g][0] = t4[0]; b[2*g][1] = t4[1];
                b[2*g+1][0] = t4[2]; b[2*g+1][1] = t4[3];
            }
            #pragma unroll
            for (int mt = 0; mt < 2; mt++)
                #pragma unroll
                for (int nt = 0; nt < 4; nt++)
                    mma_f16(acc[mt][nt], a[mt], b[nt]);
        }

        load_stage(kt + 3);
        asm volatile("cp.async.commit_group;");
    }

    const int rbase = m0 + warp_m + (lane >> 2);
    const int cbase = n0 + warp_n + 2 * (lane & 3);
    #pragma unroll
    for (int mt = 0; mt < 2; mt++) {
        #pragma unroll
        for (int nt = 0; nt < 4; nt++) {
            int col = cbase + nt * 8;
            float2 bi = *(const float2*)(bias + col);
            #pragma unroll
            for (int half = 0; half < 2; half++) {
                int row = rbase + mt * 16 + half * 8;
                size_t ro = (size_t)row * N + col;
                float ox = acc[mt][nt][2 * half + 0] + bi.x;
                float oy = acc[mt][nt][2 * half + 1] + bi.y;
                if (do_gelu) { ox = gelu_f(ox); oy = gelu_f(oy); }
                if (res) {
                    float2 rv = *(const float2*)(res + ro);
                    ox += rv.x; oy += rv.y;
                }
                if (out_half) {
                    *(__half2*)((__half*)Cp + ro) = __floats2half2_rn(ox, oy);
                } else {
                    *(float2*)((float*)Cp + ro) = make_float2(ox, oy);
                }
            }
        }
    }
}

// ---------------- LayerNorm: one WARP per row, shfl-only ------------------
__global__ __launch_bounds__(256) void ln_kernel(
    const float* __restrict__ x, const float* __restrict__ g,
    const float* __restrict__ b, void* __restrict__ out, int out_half)
{
    int row  = blockIdx.x * 8 + (threadIdx.x >> 5);
    int lane = threadIdx.x & 31;
    const float4* xr = (const float4*)(x + (size_t)row * D_);

    float4 v[8];
    #pragma unroll
    for (int i = 0; i < 8; i++) v[i] = xr[lane + i * 32];

    float s = 0.0f;
    #pragma unroll
    for (int i = 0; i < 8; i++) s += v[i].x + v[i].y + v[i].z + v[i].w;
    #pragma unroll
    for (int o = 16; o; o >>= 1) s += __shfl_xor_sync(0xffffffffu, s, o);
    float mu = s * (1.0f / D_);

    float s2 = 0.0f;
    #pragma unroll
    for (int i = 0; i < 8; i++) {
        float dx = v[i].x - mu, dy = v[i].y - mu, dz = v[i].z - mu, dw = v[i].w - mu;
        s2 += dx*dx + dy*dy + dz*dz + dw*dw;
    }
    #pragma unroll
    for (int o = 16; o; o >>= 1) s2 += __shfl_xor_sync(0xffffffffu, s2, o);
    float rstd = rsqrtf(s2 * (1.0f / D_) + 1e-5f);

    const float4* gr = (const float4*)g;
    const float4* br = (const float4*)b;
    #pragma unroll
    for (int i = 0; i < 8; i++) {
        float4 gv = gr[lane + i * 32];
        float4 bv = br[lane + i * 32];
        float ox = (v[i].x - mu) * rstd * gv.x + bv.x;
        float oy = (v[i].y - mu) * rstd * gv.y + bv.y;
        float oz = (v[i].z - mu) * rstd * gv.z + bv.z;
        float ow = (v[i].w - mu) * rstd * gv.w + bv.w;
        if (out_half) {
            __half2* po = (__half2*)((__half*)out + (size_t)row * D_ + 4 * (lane + i * 32));
            po[0] = __floats2half2_rn(ox, oy);
            po[1] = __floats2half2_rn(oz, ow);
        } else {
            ((float4*)((float*)out + (size_t)row * D_))[lane + i * 32] =
                make_float4(ox, oy, oz, ow);
        }
    }
}

// ---------------- tree-relative attention: one warp per (b,h,l) ----------
__global__ __launch_bounds__(256) void attn_kernel(
    const __half* __restrict__ qkv, const int* __restrict__ pos,
    const float* __restrict__ rq, const float* __restrict__ rk,
    const float* __restrict__ rv, __half* __restrict__ ctx)
{
    int gw   = blockIdx.x * (blockDim.x >> 5) + (threadIdx.x >> 5);
    int lane = threadIdx.x & 31;
    int l  = gw & (L_ - 1);
    int bh = gw >> 10;
    int h  = bh & (H_ - 1);
    int b  = bh >> 4;

    size_t qoff = (size_t)(b * L_ + l) * QSTR + h * DK_ + lane * 2;
    float2 qv = __half22float2(*(const __half2*)(qkv + qoff));
    const int* pp = pos + ((size_t)(b * H_ + h) * R_) * L_ + l;
    const __half* kb = qkv + D_   + (size_t)h * DK_ + lane * 2;
    const __half* vb = qkv + 2*D_ + (size_t)h * DK_ + lane * 2;

    float sc[R_];
    int   idxs[R_];
    #pragma unroll
    for (int r = 0; r < R_; r++) {
        int idx = pp[(size_t)r * L_];
        idxs[r] = idx;
        float2 rqv = *(const float2*)(rq + (h * R_ + r) * DK_ + lane * 2);
        float2 rkv = *(const float2*)(rk + (h * R_ + r) * DK_ + lane * 2);
        float2 kg  = __half22float2(*(const __half2*)(kb + (size_t)(b * L_ + idx) * QSTR));
        float p = (qv.x + rqv.x) * kg.x + (qv.y + rqv.y) * kg.y
                +  qv.x * rkv.x + qv.y * rkv.y;
        #pragma unroll
        for (int o = 16; o; o >>= 1) p += __shfl_xor_sync(0xffffffffu, p, o);
        sc[r] = (idx != l) ? p * 0.125f : -1e9f;
    }

    float m = sc[0];
    #pragma unroll
    for (int r = 1; r < R_; r++) m = fmaxf(m, sc[r]);
    float s = 0.0f;
    #pragma unroll
    for (int r = 0; r < R_; r++) { sc[r] = __expf(sc[r] - m); s += sc[r]; }
    float inv = 1.0f / s;

    float ax = 0.0f, ay = 0.0f;
    #pragma unroll
    for (int r = 0; r < R_; r++) {
        float a = sc[r] * inv;
        float2 rvv = *(const float2*)(rv + (h * R_ + r) * DK_ + lane * 2);
        float2 vg  = __half22float2(*(const __half2*)(vb + (size_t)(b * L_ + idxs[r]) * QSTR));
        ax = fmaf(a, vg.x + rvv.x, ax);
        ay = fmaf(a, vg.y + rvv.y, ay);
    }
    size_t coff = (size_t)(b * L_ + l) * D_ + h * DK_ + lane * 2;
    *(__half2*)(ctx + coff) = __floats2half2_rn(ax, ay);
}

// ---------------- host orchestration -------------------------------------
extern "C" void kernel_launch(void* const* d_in, const int* in_sizes, int n_in,
                              void* d_out, int out_size)
{
    const float* emb    = (const float*)d_in[0];
    const int*   pos    = (const int*)  d_in[1];
    const float* rel_q  = (const float*)d_in[2];
    const float* rel_k  = (const float*)d_in[3];
    const float* rel_v  = (const float*)d_in[4];
    const float* attn_w = (const float*)d_in[5];
    const float* attn_b = (const float*)d_in[6];
    const float* ff_w1  = (const float*)d_in[7];
    const float* ff_b1  = (const float*)d_in[8];
    const float* ff_w2  = (const float*)d_in[9];
    const float* ff_b2  = (const float*)d_in[10];
    const float* ln_g   = (const float*)d_in[11];
    const float* ln_b   = (const float*)d_in[12];
    const float* fin_g  = (const float*)d_in[13];
    const float* fin_b  = (const float*)d_in[14];
    float* out = (float*)d_out;

    float *x;
    __half *h, *qkv, *ctx, *ff, *wta, *wtf1, *wtf2;
    cudaGetSymbolAddress((void**)&x,    g_x);
    cudaGetSymbolAddress((void**)&h,    g_h);
    cudaGetSymbolAddress((void**)&qkv,  g_qkv);
    cudaGetSymbolAddress((void**)&ctx,  g_ctx);
    cudaGetSymbolAddress((void**)&ff,   g_ff);
    cudaGetSymbolAddress((void**)&wta,  g_wt_attn);
    cudaGetSymbolAddress((void**)&wtf1, g_wt_ff1);
    cudaGetSymbolAddress((void**)&wtf2, g_wt_ff2);

    static bool attr_done = false;
    if (!attr_done) {
        cudaFuncSetAttribute(tc_gemm128, cudaFuncAttributeMaxDynamicSharedMemorySize, GEMM_SMEM);
        cudaFuncSetAttribute(tc_gemm64,  cudaFuncAttributeMaxDynamicSharedMemorySize, GEMM_SMEM);
        attr_done = true;
    }

    // ---- weight transposes: W[K][N] f32 -> Wt[N][K] f16 ----
    transpose_k<<<dim3(D_/32, D_/32, NL_*4), dim3(32,8)>>>(attn_w, wta,  D_, D_);
    transpose_k<<<dim3(F_/32, D_/32, NL_),   dim3(32,8)>>>(ff_w1,  wtf1, D_, F_);
    transpose_k<<<dim3(D_/32, F_/32, NL_),   dim3(32,8)>>>(ff_w2,  wtf2, F_, D_);

    dim3 gQKV(3*D_/128, ROWS_/128);   // (24, 16) = 384 CTAs (128-wide tiles)
    dim3 gD64(D_/64, ROWS_/128);      // (16, 16) = 256 CTAs (64-wide tiles)
    dim3 gF(F_/128, ROWS_/128);       // (32, 16) = 512 CTAs (128-wide tiles)
    int attn_blocks = (B_ * H_ * L_) / 8;

    for (int i = 0; i < NL_; i++) {
        const float* xin = (i == 0) ? emb : x;
        const __half* Wt = wta + (size_t)i * 4 * D_ * D_;
        const float* Bb = attn_b + (size_t)i * 4 * D_;

        ln_kernel<<<ROWS_/8, 256>>>(xin, ln_g + (size_t)(i*2) * D_, ln_b + (size_t)(i*2) * D_, h, 1);

        tc_gemm128<<<gQKV, 256, GEMM_SMEM>>>(h, Wt, Bb, nullptr, qkv, ROWS_, QSTR, D_, 0, 1);

        attn_kernel<<<attn_blocks, 256>>>(qkv, pos, rel_q, rel_k, rel_v, ctx);

        tc_gemm64<<<gD64, 256, GEMM_SMEM>>>(ctx, Wt + (size_t)3*D_*D_, Bb + 3*D_, xin, x, ROWS_, D_, D_, 0, 0);

        ln_kernel<<<ROWS_/8, 256>>>(x, ln_g + (size_t)(i*2+1) * D_, ln_b + (size_t)(i*2+1) * D_, h, 1);

        tc_gemm128<<<gF, 256, GEMM_SMEM>>>(h,  wtf1 + (size_t)i * D_ * F_, ff_b1 + (size_t)i * F_,
                                           nullptr, ff, ROWS_, F_, D_, 1, 1);
        tc_gemm64<<<gD64, 256, GEMM_SMEM>>>(ff, wtf2 + (size_t)i * F_ * D_, ff_b2 + (size_t)i * D_,
                                            x, x, ROWS_, D_, F_, 0, 0);
    }
    ln_kernel<<<ROWS_/8, 256>>>(x, fin_g, fin_b, out, 0);
}

// round 11
// speedup vs baseline: 1.0863x; 1.0629x over previous
#include <cuda_runtime.h>
#include <cuda_fp16.h>
#include <math.h>
#include <stdint.h>

#define B_  2
#define L_  1024
#define D_  1024
#define H_  16
#define R_  16
#define DK_ 64
#define F_  4096
#define NL_ 4
#define ROWS_ (B_*L_)
#define QSTR (3*D_)

// ---------------- scratch (no runtime allocation allowed) ----------------
__device__ float  g_x  [ROWS_*D_];
__device__ __half g_h  [ROWS_*D_];
__device__ __half g_qkv[ROWS_*3*D_];
__device__ __half g_ctx[ROWS_*D_];
__device__ __half g_ff [ROWS_*F_];
__device__ __half g_wt_attn[(size_t)NL_*4*D_*D_];
__device__ __half g_wt_ff1 [(size_t)NL_*D_*F_];
__device__ __half g_wt_ff2 [(size_t)NL_*F_*D_];

// ---------------- helpers -------------------------------------------------
__device__ __forceinline__ uint32_t smem_to_u32(const void* p) {
    uint32_t a;
    asm("{ .reg .u64 t; cvta.to.shared.u64 t, %1; cvt.u32.u64 %0, t; }" : "=r"(a) : "l"(p));
    return a;
}
__device__ __forceinline__ void cp16(uint32_t dst, const void* src) {
    asm volatile("cp.async.cg.shared.global [%0], [%1], 16;" :: "r"(dst), "l"(src));
}
__device__ __forceinline__ void ldsm_x4(uint32_t* r, uint32_t addr) {
    asm volatile("ldmatrix.sync.aligned.m8n8.x4.shared.b16 {%0,%1,%2,%3}, [%4];"
        : "=r"(r[0]), "=r"(r[1]), "=r"(r[2]), "=r"(r[3]) : "r"(addr));
}
__device__ __forceinline__ void mma_f16(float* c, const uint32_t* a, const uint32_t* b) {
    asm volatile(
        "mma.sync.aligned.m16n8k16.row.col.f32.f16.f16.f32 "
        "{%0,%1,%2,%3}, {%4,%5,%6,%7}, {%8,%9}, {%0,%1,%2,%3};"
        : "+f"(c[0]), "+f"(c[1]), "+f"(c[2]), "+f"(c[3])
        : "r"(a[0]), "r"(a[1]), "r"(a[2]), "r"(a[3]), "r"(b[0]), "r"(b[1]));
}
__device__ __forceinline__ float gelu_f(float x) {
    float x3 = x * x * x;
    return 0.5f * x * (1.0f + tanhf(0.7978845608028654f * (x + 0.044715f * x3)));
}

// ---------------- weight transpose (src [K][N] f32 -> dst [N][K] f16) ------
// tile: 32 N-cols x 64 K-rows; half2 stores = full 128B rows.
// row stride 66 floats (264B) keeps &t[r][2*tx] 8-byte aligned for float2.
__global__ __launch_bounds__(256) void transpose_k(
    const float* __restrict__ src, __half* __restrict__ dst, int K, int N)
{
    __shared__ float t[32][66];
    src += (size_t)blockIdx.z * K * N;
    dst += (size_t)blockIdx.z * K * N;
    int n0 = blockIdx.x * 32, k0 = blockIdx.y * 64;
    int tx = threadIdx.x, ty = threadIdx.y;   // 32 x 8
    #pragma unroll
    for (int i = 0; i < 8; i++)
        t[tx][ty + i * 8] = src[(size_t)(k0 + ty + i * 8) * N + n0 + tx];
    __syncthreads();
    #pragma unroll
    for (int i = 0; i < 4; i++) {
        int r = ty + i * 8;                    // n-row 0..31
        float2 v = *(const float2*)&t[r][2 * tx];
        *(__half2*)(dst + (size_t)(n0 + r) * K + k0 + 2 * tx) =
            __floats2half2_rn(v.x, v.y);
    }
}

// ---------------- shared GEMM constants ----------------
#define BKG   64             // K elements per stage (128 bytes fp16)
#define ROWB  144            // bytes per smem row (128B data + 16B pad)
#define HALF_ (128*ROWB)     // 18432
#define STAGE (2*HALF_)      // 36864
#define GEMM_SMEM (3*STAGE)  // 110592

// ======== GEMM: CTA 128x128, 8 warps (64x32), 3-stage, 2 CTA/SM ==========
__global__ __launch_bounds__(256, 2) void tc_gemm128(
    const __half* __restrict__ A, const __half* __restrict__ Bt,
    const float* __restrict__ bias, const float* __restrict__ res,
    void* __restrict__ Cp, int M, int N, int K, int do_gelu, int out_half)
{
    extern __shared__ char smem[];
    const uint32_t sb = smem_to_u32(smem);
    const int tid  = threadIdx.x;
    const int wid  = tid >> 5;
    const int lane = tid & 31;

    const int m0 = blockIdx.y * 128;
    const int n0 = blockIdx.x * 128;
    const int KT = K / BKG;

    const int warp_m = (wid >> 2) * 64;
    const int warp_n = (wid & 3) * 32;

    const uint32_t a_off = (uint32_t)(warp_m + (lane & 15)) * ROWB
                         + (uint32_t)(lane >> 4) * 16;
    const uint32_t b_off = (uint32_t)(warp_n + (lane & 7) + ((lane >> 4) << 3)) * ROWB
                         + (uint32_t)((lane >> 3) & 1) * 16;

    float acc[4][4][4];
    #pragma unroll
    for (int i = 0; i < 4; i++)
        #pragma unroll
        for (int j = 0; j < 4; j++)
            #pragma unroll
            for (int v = 0; v < 4; v++) acc[i][j][v] = 0.0f;

    auto load_stage = [&](int kt) {
        if (kt >= KT) return;
        int s = kt % 3;
        uint32_t dA = sb + s * STAGE;
        uint32_t dB = dA + HALF_;
        int kbase = kt * BKG;
        #pragma unroll
        for (int i = 0; i < 4; i++) {
            int c = tid + i * 256;
            int row = c >> 3, kk = c & 7;
            cp16(dA + row * ROWB + kk * 16,
                 A + (size_t)(m0 + row) * K + kbase + kk * 8);
        }
        #pragma unroll
        for (int i = 0; i < 4; i++) {
            int c = tid + i * 256;
            int row = c >> 3, kk = c & 7;
            cp16(dB + row * ROWB + kk * 16,
                 Bt + (size_t)(n0 + row) * K + kbase + kk * 8);
        }
    };

    load_stage(0); asm volatile("cp.async.commit_group;");
    load_stage(1); asm volatile("cp.async.commit_group;");

    for (int kt = 0; kt < KT; kt++) {
        asm volatile("cp.async.wait_group 1;");
        __syncthreads();

        int s = kt % 3;
        uint32_t sA = sb + s * STAGE;
        uint32_t sB = sA + HALF_;

        #pragma unroll
        for (int ks = 0; ks < 4; ks++) {
            uint32_t a[4][4], b[4][2];
            #pragma unroll
            for (int mt = 0; mt < 4; mt++)
                ldsm_x4(a[mt], sA + a_off + (uint32_t)mt * (16 * ROWB) + ks * 32);
            #pragma unroll
            for (int g = 0; g < 2; g++) {
                uint32_t t4[4];
                ldsm_x4(t4, sB + b_off + (uint32_t)g * (16 * ROWB) + ks * 32);
                b[2*g][0] = t4[0]; b[2*g][1] = t4[1];
                b[2*g+1][0] = t4[2]; b[2*g+1][1] = t4[3];
            }
            #pragma unroll
            for (int mt = 0; mt < 4; mt++)
                #pragma unroll
                for (int nt = 0; nt < 4; nt++)
                    mma_f16(acc[mt][nt], a[mt], b[nt]);
        }

        load_stage(kt + 2);
        asm volatile("cp.async.commit_group;");
    }

    const int rbase = m0 + warp_m + (lane >> 2);
    const int cbase = n0 + warp_n + 2 * (lane & 3);
    #pragma unroll
    for (int mt = 0; mt < 4; mt++) {
        #pragma unroll
        for (int nt = 0; nt < 4; nt++) {
            int col = cbase + nt * 8;
            float2 bi = *(const float2*)(bias + col);
            #pragma unroll
            for (int half = 0; half < 2; half++) {
                int row = rbase + mt * 16 + half * 8;
                size_t ro = (size_t)row * N + col;
                float ox = acc[mt][nt][2 * half + 0] + bi.x;
                float oy = acc[mt][nt][2 * half + 1] + bi.y;
                if (do_gelu) { ox = gelu_f(ox); oy = gelu_f(oy); }
                if (res) {
                    float2 rv = *(const float2*)(res + ro);
                    ox += rv.x; oy += rv.y;
                }
                if (out_half) {
                    *(__half2*)((__half*)Cp + ro) = __floats2half2_rn(ox, oy);
                } else {
                    *(float2*)((float*)Cp + ro) = make_float2(ox, oy);
                }
            }
        }
    }
}

// ======== split-K GEMM: same mainloop, f32 atomicAdd epilogue ============
// grid.z = 2 splits; accumulates IN-PLACE into live C (residual base).
// split 0 adds bias; partial sums land via atomicAdd.
__global__ __launch_bounds__(256, 2) void tc_gemm_sk(
    const __half* __restrict__ A, const __half* __restrict__ Bt,
    const float* __restrict__ bias,
    float* __restrict__ C, int M, int N, int K)
{
    extern __shared__ char smem[];
    const uint32_t sb = smem_to_u32(smem);
    const int tid  = threadIdx.x;
    const int wid  = tid >> 5;
    const int lane = tid & 31;

    const int m0 = blockIdx.y * 128;
    const int n0 = blockIdx.x * 128;
    const int z  = blockIdx.z;
    const int Kh = K >> 1;
    const int kz = z * Kh;
    const int KT = Kh / BKG;

    const int warp_m = (wid >> 2) * 64;
    const int warp_n = (wid & 3) * 32;

    const uint32_t a_off = (uint32_t)(warp_m + (lane & 15)) * ROWB
                         + (uint32_t)(lane >> 4) * 16;
    const uint32_t b_off = (uint32_t)(warp_n + (lane & 7) + ((lane >> 4) << 3)) * ROWB
                         + (uint32_t)((lane >> 3) & 1) * 16;

    float acc[4][4][4];
    #pragma unroll
    for (int i = 0; i < 4; i++)
        #pragma unroll
        for (int j = 0; j < 4; j++)
            #pragma unroll
            for (int v = 0; v < 4; v++) acc[i][j][v] = 0.0f;

    auto load_stage = [&](int kt) {
        if (kt >= KT) return;
        int s = kt % 3;
        uint32_t dA = sb + s * STAGE;
        uint32_t dB = dA + HALF_;
        int kbase = kz + kt * BKG;
        #pragma unroll
        for (int i = 0; i < 4; i++) {
            int c = tid + i * 256;
            int row = c >> 3, kk = c & 7;
            cp16(dA + row * ROWB + kk * 16,
                 A + (size_t)(m0 + row) * K + kbase + kk * 8);
        }
        #pragma unroll
        for (int i = 0; i < 4; i++) {
            int c = tid + i * 256;
            int row = c >> 3, kk = c & 7;
            cp16(dB + row * ROWB + kk * 16,
                 Bt + (size_t)(n0 + row) * K + kbase + kk * 8);
        }
    };

    load_stage(0); asm volatile("cp.async.commit_group;");
    load_stage(1); asm volatile("cp.async.commit_group;");

    for (int kt = 0; kt < KT; kt++) {
        asm volatile("cp.async.wait_group 1;");
        __syncthreads();

        int s = kt % 3;
        uint32_t sA = sb + s * STAGE;
        uint32_t sB = sA + HALF_;

        #pragma unroll
        for (int ks = 0; ks < 4; ks++) {
            uint32_t a[4][4], b[4][2];
            #pragma unroll
            for (int mt = 0; mt < 4; mt++)
                ldsm_x4(a[mt], sA + a_off + (uint32_t)mt * (16 * ROWB) + ks * 32);
            #pragma unroll
            for (int g = 0; g < 2; g++) {
                uint32_t t4[4];
                ldsm_x4(t4, sB + b_off + (uint32_t)g * (16 * ROWB) + ks * 32);
                b[2*g][0] = t4[0]; b[2*g][1] = t4[1];
                b[2*g+1][0] = t4[2]; b[2*g+1][1] = t4[3];
            }
            #pragma unroll
            for (int mt = 0; mt < 4; mt++)
                #pragma unroll
                for (int nt = 0; nt < 4; nt++)
                    mma_f16(acc[mt][nt], a[mt], b[nt]);
        }

        load_stage(kt + 2);
        asm volatile("cp.async.commit_group;");
    }

    const int rbase = m0 + warp_m + (lane >> 2);
    const int cbase = n0 + warp_n + 2 * (lane & 3);
    #pragma unroll
    for (int mt = 0; mt < 4; mt++) {
        #pragma unroll
        for (int nt = 0; nt < 4; nt++) {
            int col = cbase + nt * 8;
            float bx = 0.0f, by = 0.0f;
            if (z == 0) {
                float2 bi = *(const float2*)(bias + col);
                bx = bi.x; by = bi.y;
            }
            #pragma unroll
            for (int half = 0; half < 2; half++) {
                int row = rbase + mt * 16 + half * 8;
                size_t ro = (size_t)row * N + col;
                atomicAdd(C + ro,     acc[mt][nt][2 * half + 0] + bx);
                atomicAdd(C + ro + 1, acc[mt][nt][2 * half + 1] + by);
            }
        }
    }
}

// ---------------- LayerNorm: one block per row, D=1024, 256 thr ----------
__global__ __launch_bounds__(256) void ln_kernel(
    const float* __restrict__ x, const float* __restrict__ g,
    const float* __restrict__ b, void* __restrict__ out, int out_half)
{
    int row = blockIdx.x;
    int t = threadIdx.x;
    const float4* xr = (const float4*)(x + (size_t)row * D_);
    float4 v = xr[t];

    __shared__ float red[8];
    float s = v.x + v.y + v.z + v.w;
    #pragma unroll
    for (int o = 16; o; o >>= 1) s += __shfl_xor_sync(0xffffffffu, s, o);
    if ((t & 31) == 0) red[t >> 5] = s;
    __syncthreads();
    float tot = red[0];
    #pragma unroll
    for (int w = 1; w < 8; w++) tot += red[w];
    float mu = tot * (1.0f / D_);
    float dx = v.x - mu, dy = v.y - mu, dz = v.z - mu, dw = v.w - mu;
    __syncthreads();
    float s2 = dx*dx + dy*dy + dz*dz + dw*dw;
    #pragma unroll
    for (int o = 16; o; o >>= 1) s2 += __shfl_xor_sync(0xffffffffu, s2, o);
    if ((t & 31) == 0) red[t >> 5] = s2;
    __syncthreads();
    float tot2 = red[0];
    #pragma unroll
    for (int w = 1; w < 8; w++) tot2 += red[w];
    float rstd = rsqrtf(tot2 * (1.0f / D_) + 1e-5f);

    float4 gv = ((const float4*)g)[t];
    float4 bv = ((const float4*)b)[t];
    float ox = dx * rstd * gv.x + bv.x;
    float oy = dy * rstd * gv.y + bv.y;
    float oz = dz * rstd * gv.z + bv.z;
    float ow = dw * rstd * gv.w + bv.w;
    if (out_half) {
        __half2* po = (__half2*)((__half*)out + (size_t)row * D_) + t * 2;
        po[0] = __floats2half2_rn(ox, oy);
        po[1] = __floats2half2_rn(oz, ow);
    } else {
        ((float4*)((float*)out + (size_t)row * D_))[t] = make_float4(ox, oy, oz, ow);
    }
}

// ---------------- tree-relative attention: one warp per (b,h,l) ----------
__global__ __launch_bounds__(256) void attn_kernel(
    const __half* __restrict__ qkv, const int* __restrict__ pos,
    const float* __restrict__ rq, const float* __restrict__ rk,
    const float* __restrict__ rv, __half* __restrict__ ctx)
{
    int gw   = blockIdx.x * (blockDim.x >> 5) + (threadIdx.x >> 5);
    int lane = threadIdx.x & 31;
    int l  = gw & (L_ - 1);
    int bh = gw >> 10;
    int h  = bh & (H_ - 1);
    int b  = bh >> 4;

    size_t qoff = (size_t)(b * L_ + l) * QSTR + h * DK_ + lane * 2;
    float2 qv = __half22float2(*(const __half2*)(qkv + qoff));
    const int* pp = pos + ((size_t)(b * H_ + h) * R_) * L_ + l;
    const __half* kb = qkv + D_   + (size_t)h * DK_ + lane * 2;
    const __half* vb = qkv + 2*D_ + (size_t)h * DK_ + lane * 2;

    float sc[R_];
    int   idxs[R_];
    #pragma unroll
    for (int r = 0; r < R_; r++) {
        int idx = pp[(size_t)r * L_];
        idxs[r] = idx;
        float2 rqv = *(const float2*)(rq + (h * R_ + r) * DK_ + lane * 2);
        float2 rkv = *(const float2*)(rk + (h * R_ + r) * DK_ + lane * 2);
        float2 kg  = __half22float2(*(const __half2*)(kb + (size_t)(b * L_ + idx) * QSTR));
        float p = (qv.x + rqv.x) * kg.x + (qv.y + rqv.y) * kg.y
                +  qv.x * rkv.x + qv.y * rkv.y;
        #pragma unroll
        for (int o = 16; o; o >>= 1) p += __shfl_xor_sync(0xffffffffu, p, o);
        sc[r] = (idx != l) ? p * 0.125f : -1e9f;
    }

    float m = sc[0];
    #pragma unroll
    for (int r = 1; r < R_; r++) m = fmaxf(m, sc[r]);
    float s = 0.0f;
    #pragma unroll
    for (int r = 0; r < R_; r++) { sc[r] = __expf(sc[r] - m); s += sc[r]; }
    float inv = 1.0f / s;

    float ax = 0.0f, ay = 0.0f;
    #pragma unroll
    for (int r = 0; r < R_; r++) {
        float a = sc[r] * inv;
        float2 rvv = *(const float2*)(rv + (h * R_ + r) * DK_ + lane * 2);
        float2 vg  = __half22float2(*(const __half2*)(vb + (size_t)(b * L_ + idxs[r]) * QSTR));
        ax = fmaf(a, vg.x + rvv.x, ax);
        ay = fmaf(a, vg.y + rvv.y, ay);
    }
    size_t coff = (size_t)(b * L_ + l) * D_ + h * DK_ + lane * 2;
    *(__half2*)(ctx + coff) = __floats2half2_rn(ax, ay);
}

// ---------------- host orchestration -------------------------------------
extern "C" void kernel_launch(void* const* d_in, const int* in_sizes, int n_in,
                              void* d_out, int out_size)
{
    const float* emb    = (const float*)d_in[0];
    const int*   pos    = (const int*)  d_in[1];
    const float* rel_q  = (const float*)d_in[2];
    const float* rel_k  = (const float*)d_in[3];
    const float* rel_v  = (const float*)d_in[4];
    const float* attn_w = (const float*)d_in[5];
    const float* attn_b = (const float*)d_in[6];
    const float* ff_w1  = (const float*)d_in[7];
    const float* ff_b1  = (const float*)d_in[8];
    const float* ff_w2  = (const float*)d_in[9];
    const float* ff_b2  = (const float*)d_in[10];
    const float* ln_g   = (const float*)d_in[11];
    const float* ln_b   = (const float*)d_in[12];
    const float* fin_g  = (const float*)d_in[13];
    const float* fin_b  = (const float*)d_in[14];
    float* out = (float*)d_out;

    float *x;
    __half *h, *qkv, *ctx, *ff, *wta, *wtf1, *wtf2;
    cudaGetSymbolAddress((void**)&x,    g_x);
    cudaGetSymbolAddress((void**)&h,    g_h);
    cudaGetSymbolAddress((void**)&qkv,  g_qkv);
    cudaGetSymbolAddress((void**)&ctx,  g_ctx);
    cudaGetSymbolAddress((void**)&ff,   g_ff);
    cudaGetSymbolAddress((void**)&wta,  g_wt_attn);
    cudaGetSymbolAddress((void**)&wtf1, g_wt_ff1);
    cudaGetSymbolAddress((void**)&wtf2, g_wt_ff2);

    static bool attr_done = false;
    if (!attr_done) {
        cudaFuncSetAttribute(tc_gemm128, cudaFuncAttributeMaxDynamicSharedMemorySize, GEMM_SMEM);
        cudaFuncSetAttribute(tc_gemm_sk, cudaFuncAttributeMaxDynamicSharedMemorySize, GEMM_SMEM);
        attr_done = true;
    }

    // residual stream bootstrap: x = emb (O-proj/FF2 accumulate in place)
    cudaMemcpyAsync(x, emb, (size_t)ROWS_ * D_ * sizeof(float),
                    cudaMemcpyDeviceToDevice, 0);

    // ---- weight transposes: W[K][N] f32 -> Wt[N][K] f16 ----
    transpose_k<<<dim3(D_/32, D_/64, NL_*4), dim3(32,8)>>>(attn_w, wta,  D_, D_);
    transpose_k<<<dim3(F_/32, D_/64, NL_),   dim3(32,8)>>>(ff_w1,  wtf1, D_, F_);
    transpose_k<<<dim3(D_/32, F_/64, NL_),   dim3(32,8)>>>(ff_w2,  wtf2, F_, D_);

    dim3 gQKV(3*D_/128, ROWS_/128);        // (24, 16) = 384 CTAs
    dim3 gSK(D_/128, ROWS_/128, 2);        // (8, 16, 2) = 256 CTAs split-K
    dim3 gF(F_/128, ROWS_/128);            // (32, 16) = 512 CTAs
    int attn_blocks = (B_ * H_ * L_) / 8;

    for (int i = 0; i < NL_; i++) {
        const __half* Wt = wta + (size_t)i * 4 * D_ * D_;
        const float* Bb = attn_b + (size_t)i * 4 * D_;

        ln_kernel<<<ROWS_, 256>>>(x, ln_g + (size_t)(i*2) * D_, ln_b + (size_t)(i*2) * D_, h, 1);

        tc_gemm128<<<gQKV, 256, GEMM_SMEM>>>(h, Wt, Bb, nullptr, qkv, ROWS_, QSTR, D_, 0, 1);

        attn_kernel<<<attn_blocks, 256>>>(qkv, pos, rel_q, rel_k, rel_v, ctx);

        // O-proj, split-K=2, accumulates into live x (residual in place)
        tc_gemm_sk<<<gSK, 256, GEMM_SMEM>>>(ctx, Wt + (size_t)3*D_*D_, Bb + 3*D_,
                                            x, ROWS_, D_, D_);

        ln_kernel<<<ROWS_, 256>>>(x, ln_g + (size_t)(i*2+1) * D_, ln_b + (size_t)(i*2+1) * D_, h, 1);

        tc_gemm128<<<gF, 256, GEMM_SMEM>>>(h,  ff_w1 ? wtf1 + (size_t)i * D_ * F_ : nullptr,
                                           ff_b1 + (size_t)i * F_, nullptr, ff, ROWS_, F_, D_, 1, 1);

        // FF2, split-K=2 over K=4096, accumulates into live x
        tc_gemm_sk<<<gSK, 256, GEMM_SMEM>>>(ff, wtf2 + (size_t)i * F_ * D_, ff_b2 + (size_t)i * D_,
                                            x, ROWS_, D_, F_);
    }
    ln_kernel<<<ROWS_, 256>>>(x, fin_g, fin_b, out, 0);
}